// round 4
// baseline (speedup 1.0000x reference)
#include <cuda_runtime.h>
#include <cuda_bf16.h>

#define DINL __device__ __forceinline__

namespace {
constexpr int T_ = 128, B_ = 512, I_ = 64, H_ = 512, H2_ = 1024;
constexpr int NBLK = 128, TPB = 256;
constexpr int SA = 68, SW = 100;
}

__device__ __align__(16) float g_h[B_ * H_];
__device__ __align__(16) float g_y[B_ * H_];
__device__ __align__(16) float g_acc[B_ * H_];
__device__ __align__(16) float g_u[B_ * H2_];
__device__ __align__(16) float g_G[B_ * H_];
__device__ __align__(16) float g_pGH[16 * B_];
__device__ __align__(16) float g_pHH[16 * B_];
__device__ unsigned g_count = 0;
__device__ volatile unsigned g_gen = 0;

DINL void gridbar() {
  __threadfence();
  __syncthreads();
  if (threadIdx.x == 0) {
    unsigned gen = g_gen;
    if (atomicAdd(&g_count, 1u) == NBLK - 1u) {
      g_count = 0u;
      __threadfence();
      g_gen = gen + 1u;
    } else {
      while (g_gen == gen) __nanosleep(32);
    }
    __threadfence();
  }
  __syncthreads();
}

DINL float sigf(float x) { return __fdividef(1.f, 1.f + __expf(-x)); }

// Stage a ROWS x 16 tile of row-major src (pre-offset to row0/k0) transposed
// into smem: s[k * stride + r]. One float4 per (r,q) pair.
template <bool CG, int ROWS>
DINL void stageT(float* s, int stride, const float* src, int ld, int tid) {
#pragma unroll
  for (int i = tid; i < ROWS * 4; i += TPB) {
    int r = i >> 2, q = i & 3;
    const float4* p = reinterpret_cast<const float4*>(src + (size_t)r * ld + q * 4);
    float4 v = CG ? __ldcg(p) : __ldg(p);
    s[(q * 4 + 0) * stride + r] = v.x;
    s[(q * 4 + 1) * stride + r] = v.y;
    s[(q * 4 + 2) * stride + r] = v.z;
    s[(q * 4 + 3) * stride + r] = v.w;
  }
}

__global__ void __launch_bounds__(TPB, 1)
ode_kernel(const float* __restrict__ seq, const float* __restrict__ dts,
           const float* __restrict__ w_ih, const float* __restrict__ w_hh,
           const float* __restrict__ b_ih, const float* __restrict__ b_hh,
           const float* __restrict__ w1, const float* __restrict__ b1,
           const float* __restrict__ w2, const float* __restrict__ b2,
           float* __restrict__ out) {
  __shared__ __align__(16) float sA[16 * SA];
  __shared__ __align__(16) float sW[16 * SW];
  const int tid = threadIdx.x, bid = blockIdx.x;
  const int ty = tid >> 4, tx = tid & 15;
  const int rb = bid >> 4, cb = bid & 15;
  const int row0 = rb * 64, col32 = cb * 32, col64 = cb * 64;

  for (int i = bid * TPB + tid; i < B_ * H_; i += NBLK * TPB) g_h[i] = 0.f;
  gridbar();

  for (int t = 0; t < T_; ++t) {
    const float dt = __ldg(dts + t);

    // ---------------- GRU: h_rnn tile 64x32, gates fused ----------------
    {
      float aR[4][2] = {}, aZ[4][2] = {}, aNi[4][2] = {}, aNh[4][2] = {};
      for (int k0 = 0; k0 < H_; k0 += 16) {  // h @ w_hh^T
        stageT<true, 64>(sA, SA, g_h + (size_t)row0 * H_ + k0, H_, tid);
        stageT<false, 32>(sW + 0, SW, w_hh + (size_t)(col32) * H_ + k0, H_, tid);
        stageT<false, 32>(sW + 32, SW, w_hh + (size_t)(512 + col32) * H_ + k0, H_, tid);
        stageT<false, 32>(sW + 64, SW, w_hh + (size_t)(1024 + col32) * H_ + k0, H_, tid);
        __syncthreads();
#pragma unroll
        for (int kk = 0; kk < 16; ++kk) {
          float4 a = *reinterpret_cast<const float4*>(&sA[kk * SA + ty * 4]);
          float2 br = *reinterpret_cast<const float2*>(&sW[kk * SW + tx * 2]);
          float2 bz = *reinterpret_cast<const float2*>(&sW[kk * SW + 32 + tx * 2]);
          float2 bn = *reinterpret_cast<const float2*>(&sW[kk * SW + 64 + tx * 2]);
          float av[4] = {a.x, a.y, a.z, a.w};
#pragma unroll
          for (int i = 0; i < 4; ++i) {
            aR[i][0] = fmaf(av[i], br.x, aR[i][0]);
            aR[i][1] = fmaf(av[i], br.y, aR[i][1]);
            aZ[i][0] = fmaf(av[i], bz.x, aZ[i][0]);
            aZ[i][1] = fmaf(av[i], bz.y, aZ[i][1]);
            aNh[i][0] = fmaf(av[i], bn.x, aNh[i][0]);
            aNh[i][1] = fmaf(av[i], bn.y, aNh[i][1]);
          }
        }
        __syncthreads();
      }
      for (int k0 = 0; k0 < I_; k0 += 16) {  // x @ w_ih^T
        stageT<false, 64>(sA, SA, seq + (size_t)t * B_ * I_ + (size_t)row0 * I_ + k0, I_, tid);
        stageT<false, 32>(sW + 0, SW, w_ih + (size_t)(col32) * I_ + k0, I_, tid);
        stageT<false, 32>(sW + 32, SW, w_ih + (size_t)(512 + col32) * I_ + k0, I_, tid);
        stageT<false, 32>(sW + 64, SW, w_ih + (size_t)(1024 + col32) * I_ + k0, I_, tid);
        __syncthreads();
#pragma unroll
        for (int kk = 0; kk < 16; ++kk) {
          float4 a = *reinterpret_cast<const float4*>(&sA[kk * SA + ty * 4]);
          float2 br = *reinterpret_cast<const float2*>(&sW[kk * SW + tx * 2]);
          float2 bz = *reinterpret_cast<const float2*>(&sW[kk * SW + 32 + tx * 2]);
          float2 bn = *reinterpret_cast<const float2*>(&sW[kk * SW + 64 + tx * 2]);
          float av[4] = {a.x, a.y, a.z, a.w};
#pragma unroll
          for (int i = 0; i < 4; ++i) {
            aR[i][0] = fmaf(av[i], br.x, aR[i][0]);
            aR[i][1] = fmaf(av[i], br.y, aR[i][1]);
            aZ[i][0] = fmaf(av[i], bz.x, aZ[i][0]);
            aZ[i][1] = fmaf(av[i], bz.y, aZ[i][1]);
            aNi[i][0] = fmaf(av[i], bn.x, aNi[i][0]);
            aNi[i][1] = fmaf(av[i], bn.y, aNi[i][1]);
          }
        }
        __syncthreads();
      }
#pragma unroll
      for (int i = 0; i < 4; ++i) {
        int r = row0 + ty * 4 + i;
#pragma unroll
        for (int j = 0; j < 2; ++j) {
          int c = col32 + tx * 2 + j;
          float rr = sigf(aR[i][j] + __ldg(b_ih + c) + __ldg(b_hh + c));
          float zz = sigf(aZ[i][j] + __ldg(b_ih + 512 + c) + __ldg(b_hh + 512 + c));
          float nn = tanhf(aNi[i][j] + __ldg(b_ih + 1024 + c) +
                           rr * (aNh[i][j] + __ldg(b_hh + 1024 + c)));
          float hp = __ldcg(&g_h[(size_t)r * H_ + c]);
          float hn = (1.f - zz) * nn + zz * hp;
          out[(size_t)t * B_ * H_ + (size_t)r * H_ + c] = hn;
          g_y[(size_t)r * H_ + c] = hn;
        }
      }
    }
    gridbar();

    // ---------------- RK4 stages ----------------
    for (int s = 0; s < 4; ++s) {
      // mm1: u = tanh(y @ w1^T + b1), 64x64 tile
      {
        float ac[4][4] = {};
        for (int k0 = 0; k0 < H_; k0 += 16) {
          stageT<true, 64>(sA, SA, g_y + (size_t)row0 * H_ + k0, H_, tid);
          stageT<false, 64>(sW, SW, w1 + (size_t)col64 * H_ + k0, H_, tid);
          __syncthreads();
#pragma unroll
          for (int kk = 0; kk < 16; ++kk) {
            float4 a = *reinterpret_cast<const float4*>(&sA[kk * SA + ty * 4]);
            float2 w0 = *reinterpret_cast<const float2*>(&sW[kk * SW + tx * 2]);
            float2 w1v = *reinterpret_cast<const float2*>(&sW[kk * SW + 32 + tx * 2]);
            float av[4] = {a.x, a.y, a.z, a.w};
#pragma unroll
            for (int i = 0; i < 4; ++i) {
              ac[i][0] = fmaf(av[i], w0.x, ac[i][0]);
              ac[i][1] = fmaf(av[i], w0.y, ac[i][1]);
              ac[i][2] = fmaf(av[i], w1v.x, ac[i][2]);
              ac[i][3] = fmaf(av[i], w1v.y, ac[i][3]);
            }
          }
          __syncthreads();
        }
#pragma unroll
        for (int i = 0; i < 4; ++i) {
          int r = row0 + ty * 4 + i;
#pragma unroll
          for (int j = 0; j < 4; ++j) {
            int c = col64 + (j >> 1) * 32 + tx * 2 + (j & 1);
            g_u[(size_t)r * H2_ + c] = tanhf(ac[i][j] + __ldg(b1 + c));
          }
        }
      }
      gridbar();

      // mm2: G = u @ w2^T + b2 (64x32 tile) + partial dots
      {
        float ac[4][2] = {};
        for (int k0 = 0; k0 < H2_; k0 += 16) {
          stageT<true, 64>(sA, SA, g_u + (size_t)row0 * H2_ + k0, H2_, tid);
          stageT<false, 32>(sW, SW, w2 + (size_t)col32 * H2_ + k0, H2_, tid);
          __syncthreads();
#pragma unroll
          for (int kk = 0; kk < 16; ++kk) {
            float4 a = *reinterpret_cast<const float4*>(&sA[kk * SA + ty * 4]);
            float2 w = *reinterpret_cast<const float2*>(&sW[kk * SW + tx * 2]);
            float av[4] = {a.x, a.y, a.z, a.w};
#pragma unroll
            for (int i = 0; i < 4; ++i) {
              ac[i][0] = fmaf(av[i], w.x, ac[i][0]);
              ac[i][1] = fmaf(av[i], w.y, ac[i][1]);
            }
          }
          __syncthreads();
        }
        float pgh[4], phh[4];
#pragma unroll
        for (int i = 0; i < 4; ++i) {
          int r = row0 + ty * 4 + i, c0 = col32 + tx * 2;
          float G0 = ac[i][0] + __ldg(b2 + c0);
          float G1 = ac[i][1] + __ldg(b2 + c0 + 1);
          float y0 = __ldcg(&g_y[(size_t)r * H_ + c0]);
          float y1 = __ldcg(&g_y[(size_t)r * H_ + c0 + 1]);
          g_G[(size_t)r * H_ + c0] = G0;
          g_G[(size_t)r * H_ + c0 + 1] = G1;
          pgh[i] = fmaf(G0, y0, G1 * y1);
          phh[i] = fmaf(y0, y0, y1 * y1);
        }
#pragma unroll
        for (int o = 1; o < 16; o <<= 1) {
#pragma unroll
          for (int i = 0; i < 4; ++i) {
            pgh[i] += __shfl_xor_sync(0xffffffffu, pgh[i], o);
            phh[i] += __shfl_xor_sync(0xffffffffu, phh[i], o);
          }
        }
        if (tx == 0) {
#pragma unroll
          for (int i = 0; i < 4; ++i) {
            int r = row0 + ty * 4 + i;
            g_pGH[cb * B_ + r] = pgh[i];
            g_pHH[cb * B_ + r] = phh[i];
          }
        }
      }
      gridbar();

      // update: proj, k_s, RK accumulate, next y / final h
      {
        const float wk = (s == 1 || s == 2) ? 2.f : 1.f;
        int r = bid * 4 + (tid >> 6);
        int c0 = (tid & 63) * 8;
        float sgh = 0.f, shh = 0.f;
#pragma unroll
        for (int p = 0; p < 16; ++p) {
          sgh += __ldcg(&g_pGH[p * B_ + r]);
          shh += __ldcg(&g_pHH[p * B_ + r]);
        }
        float proj = sgh / (shh + 1e-8f);
        const float* hb = out + (size_t)t * B_ * H_ + (size_t)r * H_;
#pragma unroll
        for (int j = 0; j < 8; ++j) {
          int c = c0 + j;
          float y = __ldcg(&g_y[(size_t)r * H_ + c]);
          float G = __ldcg(&g_G[(size_t)r * H_ + c]);
          float k = G - proj * y;
          float a = (s == 0) ? 0.f : __ldcg(&g_acc[(size_t)r * H_ + c]);
          float na = a + wk * k;
          float hbv = __ldcg(&hb[c]);
          if (s < 3) {
            g_acc[(size_t)r * H_ + c] = na;
            float cs = (s == 2) ? 1.0f : 0.5f;
            g_y[(size_t)r * H_ + c] = hbv + cs * dt * k;
          } else {
            g_h[(size_t)r * H_ + c] = hbv + (dt * (1.f / 6.f)) * na;
          }
        }
      }
      gridbar();
    }
  }
}

extern "C" void kernel_launch(void* const* d_in, const int* in_sizes, int n_in,
                              void* d_out, int out_size) {
  (void)in_sizes; (void)n_in; (void)out_size;
  ode_kernel<<<NBLK, TPB>>>(
      (const float*)d_in[0], (const float*)d_in[1], (const float*)d_in[2],
      (const float*)d_in[3], (const float*)d_in[4], (const float*)d_in[5],
      (const float*)d_in[6], (const float*)d_in[7], (const float*)d_in[8],
      (const float*)d_in[9], (float*)d_out);
}

// round 5
// speedup vs baseline: 1.0473x; 1.0473x over previous
#include <cuda_runtime.h>

#define DINL __device__ __forceinline__

namespace {
constexpr int T_ = 128, B_ = 512, I_ = 64, H_ = 512, H2_ = 1024;
constexpr int NBLK = 128, TPB = 512;
constexpr int SA = 68, SW = 100;
}

__device__ __align__(16) float g_h[B_ * H_];
__device__ __align__(16) float g_y[B_ * H_];
__device__ __align__(16) float g_acc[B_ * H_];
__device__ __align__(16) float g_u[B_ * H2_];
__device__ __align__(16) float g_G[B_ * H_];
__device__ __align__(16) float g_pGH[16 * B_];
__device__ __align__(16) float g_pHH[16 * B_];
__device__ unsigned g_count = 0;
__device__ volatile unsigned g_gen = 0;

DINL void gridbar() {
  __threadfence();
  __syncthreads();
  if (threadIdx.x == 0) {
    unsigned gen = g_gen;
    if (atomicAdd(&g_count, 1u) == NBLK - 1u) {
      g_count = 0u;
      __threadfence();
      g_gen = gen + 1u;
    } else {
      while (g_gen == gen) __nanosleep(32);
    }
    __threadfence();
  }
  __syncthreads();
}

DINL float sigf(float x) { return __fdividef(1.f, 1.f + __expf(-x)); }

__global__ void __launch_bounds__(TPB, 1)
ode_kernel(const float* __restrict__ seq, const float* __restrict__ dts,
           const float* __restrict__ w_ih, const float* __restrict__ w_hh,
           const float* __restrict__ b_ih, const float* __restrict__ b_hh,
           const float* __restrict__ w1, const float* __restrict__ b1,
           const float* __restrict__ w2, const float* __restrict__ b2,
           float* __restrict__ out) {
  __shared__ __align__(16) float sA[2][16 * SA];
  __shared__ __align__(16) float sW[2][16 * SW];
  const int tid = threadIdx.x, bid = blockIdx.x;
  const int ty = tid >> 4, tx = tid & 15;   // ty 0..31 (2 rows), tx 0..15 (2 cols)
  const int rb = bid >> 4, cb = bid & 15;
  const int row0 = rb * 64, col32 = cb * 32, col64 = cb * 64;

  for (int i = bid * TPB + tid; i < B_ * H_; i += NBLK * TPB) g_h[i] = 0.f;
  gridbar();

  for (int t = 0; t < T_; ++t) {
    const float dt = __ldg(dts + t);

    // ================== GRU: 64x32 tile, gates fused ==================
    {
      float aR[2][2] = {}, aZ[2][2] = {}, aNi[2][2] = {}, aNh[2][2] = {};

      // ---- phase 1: h @ w_hh^T  (K=512, 32 chunks, W = 96 rows / 3 gates)
      {
        const float* Ab = g_h + (size_t)row0 * H_;
        auto pf = [&](float4* v, int c) {
          const int k0 = c * 16;
          if (tid < 256) {
            int r = tid >> 2, q = tid & 3;
            v[0] = __ldcg((const float4*)(Ab + (size_t)r * H_ + k0 + q * 4));
          } else {
            int jw = tid - 256, rw = jw >> 2, q = jw & 3;
            int gr = (rw >> 5) * 512 + col32 + (rw & 31);
            v[0] = __ldg((const float4*)(w_hh + (size_t)gr * H_ + k0 + q * 4));
          }
          if (tid < 128) {
            int jw = tid + 256, rw = jw >> 2, q = jw & 3;
            int gr = (rw >> 5) * 512 + col32 + (rw & 31);
            v[1] = __ldg((const float4*)(w_hh + (size_t)gr * H_ + k0 + q * 4));
          }
        };
        auto st = [&](const float4* v, int b) {
          if (tid < 256) {
            int r = tid >> 2, q = tid & 3;
            float* d = &sA[b][0] + r;
            d[(q * 4 + 0) * SA] = v[0].x; d[(q * 4 + 1) * SA] = v[0].y;
            d[(q * 4 + 2) * SA] = v[0].z; d[(q * 4 + 3) * SA] = v[0].w;
          } else {
            int jw = tid - 256, rw = jw >> 2, q = jw & 3;
            float* d = &sW[b][0] + rw;
            d[(q * 4 + 0) * SW] = v[0].x; d[(q * 4 + 1) * SW] = v[0].y;
            d[(q * 4 + 2) * SW] = v[0].z; d[(q * 4 + 3) * SW] = v[0].w;
          }
          if (tid < 128) {
            int jw = tid + 256, rw = jw >> 2, q = jw & 3;
            float* d = &sW[b][0] + rw;
            d[(q * 4 + 0) * SW] = v[1].x; d[(q * 4 + 1) * SW] = v[1].y;
            d[(q * 4 + 2) * SW] = v[1].z; d[(q * 4 + 3) * SW] = v[1].w;
          }
        };
        auto cmp = [&](int b) {
#pragma unroll
          for (int kk = 0; kk < 16; ++kk) {
            float2 a  = *(const float2*)&sA[b][kk * SA + ty * 2];
            float2 br = *(const float2*)&sW[b][kk * SW + tx * 2];
            float2 bz = *(const float2*)&sW[b][kk * SW + 32 + tx * 2];
            float2 bn = *(const float2*)&sW[b][kk * SW + 64 + tx * 2];
            float av[2] = {a.x, a.y};
#pragma unroll
            for (int i = 0; i < 2; ++i) {
              aR[i][0] = fmaf(av[i], br.x, aR[i][0]);
              aR[i][1] = fmaf(av[i], br.y, aR[i][1]);
              aZ[i][0] = fmaf(av[i], bz.x, aZ[i][0]);
              aZ[i][1] = fmaf(av[i], bz.y, aZ[i][1]);
              aNh[i][0] = fmaf(av[i], bn.x, aNh[i][0]);
              aNh[i][1] = fmaf(av[i], bn.y, aNh[i][1]);
            }
          }
        };
        float4 v[2];
        pf(v, 0); st(v, 0); pf(v, 1);
        __syncthreads();
        for (int c = 0; c < 32; ++c) {
          int cur = c & 1;
          if (c + 1 < 32) { st(v, cur ^ 1); if (c + 2 < 32) pf(v, c + 2); }
          cmp(cur);
          __syncthreads();
        }
      }

      // ---- phase 2: x @ w_ih^T  (K=64, 4 chunks)
      {
        const float* Ab = seq + (size_t)t * B_ * I_ + (size_t)row0 * I_;
        auto pf = [&](float4* v, int c) {
          const int k0 = c * 16;
          if (tid < 256) {
            int r = tid >> 2, q = tid & 3;
            v[0] = __ldg((const float4*)(Ab + (size_t)r * I_ + k0 + q * 4));
          } else {
            int jw = tid - 256, rw = jw >> 2, q = jw & 3;
            int gr = (rw >> 5) * 512 + col32 + (rw & 31);
            v[0] = __ldg((const float4*)(w_ih + (size_t)gr * I_ + k0 + q * 4));
          }
          if (tid < 128) {
            int jw = tid + 256, rw = jw >> 2, q = jw & 3;
            int gr = (rw >> 5) * 512 + col32 + (rw & 31);
            v[1] = __ldg((const float4*)(w_ih + (size_t)gr * I_ + k0 + q * 4));
          }
        };
        auto st = [&](const float4* v, int b) {
          if (tid < 256) {
            int r = tid >> 2, q = tid & 3;
            float* d = &sA[b][0] + r;
            d[(q * 4 + 0) * SA] = v[0].x; d[(q * 4 + 1) * SA] = v[0].y;
            d[(q * 4 + 2) * SA] = v[0].z; d[(q * 4 + 3) * SA] = v[0].w;
          } else {
            int jw = tid - 256, rw = jw >> 2, q = jw & 3;
            float* d = &sW[b][0] + rw;
            d[(q * 4 + 0) * SW] = v[0].x; d[(q * 4 + 1) * SW] = v[0].y;
            d[(q * 4 + 2) * SW] = v[0].z; d[(q * 4 + 3) * SW] = v[0].w;
          }
          if (tid < 128) {
            int jw = tid + 256, rw = jw >> 2, q = jw & 3;
            float* d = &sW[b][0] + rw;
            d[(q * 4 + 0) * SW] = v[1].x; d[(q * 4 + 1) * SW] = v[1].y;
            d[(q * 4 + 2) * SW] = v[1].z; d[(q * 4 + 3) * SW] = v[1].w;
          }
        };
        auto cmp = [&](int b) {
#pragma unroll
          for (int kk = 0; kk < 16; ++kk) {
            float2 a  = *(const float2*)&sA[b][kk * SA + ty * 2];
            float2 br = *(const float2*)&sW[b][kk * SW + tx * 2];
            float2 bz = *(const float2*)&sW[b][kk * SW + 32 + tx * 2];
            float2 bn = *(const float2*)&sW[b][kk * SW + 64 + tx * 2];
            float av[2] = {a.x, a.y};
#pragma unroll
            for (int i = 0; i < 2; ++i) {
              aR[i][0] = fmaf(av[i], br.x, aR[i][0]);
              aR[i][1] = fmaf(av[i], br.y, aR[i][1]);
              aZ[i][0] = fmaf(av[i], bz.x, aZ[i][0]);
              aZ[i][1] = fmaf(av[i], bz.y, aZ[i][1]);
              aNi[i][0] = fmaf(av[i], bn.x, aNi[i][0]);
              aNi[i][1] = fmaf(av[i], bn.y, aNi[i][1]);
            }
          }
        };
        float4 v[2];
        pf(v, 0); st(v, 0); pf(v, 1);
        __syncthreads();
        for (int c = 0; c < 4; ++c) {
          int cur = c & 1;
          if (c + 1 < 4) { st(v, cur ^ 1); if (c + 2 < 4) pf(v, c + 2); }
          cmp(cur);
          __syncthreads();
        }
      }

      // ---- GRU epilogue
#pragma unroll
      for (int i = 0; i < 2; ++i) {
        int r = row0 + ty * 2 + i;
#pragma unroll
        for (int j = 0; j < 2; ++j) {
          int c = col32 + tx * 2 + j;
          float rr = sigf(aR[i][j] + __ldg(b_ih + c) + __ldg(b_hh + c));
          float zz = sigf(aZ[i][j] + __ldg(b_ih + 512 + c) + __ldg(b_hh + 512 + c));
          float nn = tanhf(aNi[i][j] + __ldg(b_ih + 1024 + c) +
                           rr * (aNh[i][j] + __ldg(b_hh + 1024 + c)));
          float hp = __ldcg(&g_h[(size_t)r * H_ + c]);
          float hn = (1.f - zz) * nn + zz * hp;
          out[(size_t)t * B_ * H_ + (size_t)r * H_ + c] = hn;
          g_y[(size_t)r * H_ + c] = hn;
        }
      }
    }
    gridbar();

    // ================== RK4 stages ==================
    for (int s = 0; s < 4; ++s) {
      // ---- mm1: u = tanh(y @ w1^T + b1), 64x64 tile, K=512 (32 chunks)
      {
        float ac[2][4] = {};
        const float* Ab = g_y + (size_t)row0 * H_;
        auto pf = [&](float4* v, int c) {
          const int k0 = c * 16;
          if (tid < 256) {
            int r = tid >> 2, q = tid & 3;
            v[0] = __ldcg((const float4*)(Ab + (size_t)r * H_ + k0 + q * 4));
          } else {
            int jw = tid - 256, rw = jw >> 2, q = jw & 3;
            v[0] = __ldg((const float4*)(w1 + (size_t)(col64 + rw) * H_ + k0 + q * 4));
          }
        };
        auto st = [&](const float4* v, int b) {
          if (tid < 256) {
            int r = tid >> 2, q = tid & 3;
            float* d = &sA[b][0] + r;
            d[(q * 4 + 0) * SA] = v[0].x; d[(q * 4 + 1) * SA] = v[0].y;
            d[(q * 4 + 2) * SA] = v[0].z; d[(q * 4 + 3) * SA] = v[0].w;
          } else {
            int jw = tid - 256, rw = jw >> 2, q = jw & 3;
            float* d = &sW[b][0] + rw;
            d[(q * 4 + 0) * SW] = v[0].x; d[(q * 4 + 1) * SW] = v[0].y;
            d[(q * 4 + 2) * SW] = v[0].z; d[(q * 4 + 3) * SW] = v[0].w;
          }
        };
        auto cmp = [&](int b) {
#pragma unroll
          for (int kk = 0; kk < 16; ++kk) {
            float2 a  = *(const float2*)&sA[b][kk * SA + ty * 2];
            float2 w0 = *(const float2*)&sW[b][kk * SW + tx * 2];
            float2 w1v = *(const float2*)&sW[b][kk * SW + 32 + tx * 2];
            float av[2] = {a.x, a.y};
#pragma unroll
            for (int i = 0; i < 2; ++i) {
              ac[i][0] = fmaf(av[i], w0.x, ac[i][0]);
              ac[i][1] = fmaf(av[i], w0.y, ac[i][1]);
              ac[i][2] = fmaf(av[i], w1v.x, ac[i][2]);
              ac[i][3] = fmaf(av[i], w1v.y, ac[i][3]);
            }
          }
        };
        float4 v[2];
        pf(v, 0); st(v, 0); pf(v, 1);
        __syncthreads();
        for (int c = 0; c < 32; ++c) {
          int cur = c & 1;
          if (c + 1 < 32) { st(v, cur ^ 1); if (c + 2 < 32) pf(v, c + 2); }
          cmp(cur);
          __syncthreads();
        }
#pragma unroll
        for (int i = 0; i < 2; ++i) {
          int r = row0 + ty * 2 + i;
#pragma unroll
          for (int j = 0; j < 4; ++j) {
            int c = col64 + (j >> 1) * 32 + tx * 2 + (j & 1);
            g_u[(size_t)r * H2_ + c] = tanhf(ac[i][j] + __ldg(b1 + c));
          }
        }
      }
      gridbar();

      // ---- mm2: G = u @ w2^T + b2, 64x32 tile, K=1024 (64 chunks) + dots
      {
        float ac[2][2] = {};
        const float* Ab = g_u + (size_t)row0 * H2_;
        auto pf = [&](float4* v, int c) {
          const int k0 = c * 16;
          if (tid < 256) {
            int r = tid >> 2, q = tid & 3;
            v[0] = __ldcg((const float4*)(Ab + (size_t)r * H2_ + k0 + q * 4));
          } else if (tid < 384) {
            int jw = tid - 256, rw = jw >> 2, q = jw & 3;
            v[0] = __ldg((const float4*)(w2 + (size_t)(col32 + rw) * H2_ + k0 + q * 4));
          }
        };
        auto st = [&](const float4* v, int b) {
          if (tid < 256) {
            int r = tid >> 2, q = tid & 3;
            float* d = &sA[b][0] + r;
            d[(q * 4 + 0) * SA] = v[0].x; d[(q * 4 + 1) * SA] = v[0].y;
            d[(q * 4 + 2) * SA] = v[0].z; d[(q * 4 + 3) * SA] = v[0].w;
          } else if (tid < 384) {
            int jw = tid - 256, rw = jw >> 2, q = jw & 3;
            float* d = &sW[b][0] + rw;
            d[(q * 4 + 0) * SW] = v[0].x; d[(q * 4 + 1) * SW] = v[0].y;
            d[(q * 4 + 2) * SW] = v[0].z; d[(q * 4 + 3) * SW] = v[0].w;
          }
        };
        auto cmp = [&](int b) {
#pragma unroll
          for (int kk = 0; kk < 16; ++kk) {
            float2 a = *(const float2*)&sA[b][kk * SA + ty * 2];
            float2 w = *(const float2*)&sW[b][kk * SW + tx * 2];
            float av[2] = {a.x, a.y};
#pragma unroll
            for (int i = 0; i < 2; ++i) {
              ac[i][0] = fmaf(av[i], w.x, ac[i][0]);
              ac[i][1] = fmaf(av[i], w.y, ac[i][1]);
            }
          }
        };
        float4 v[2];
        pf(v, 0); st(v, 0); pf(v, 1);
        __syncthreads();
        for (int c = 0; c < 64; ++c) {
          int cur = c & 1;
          if (c + 1 < 64) { st(v, cur ^ 1); if (c + 2 < 64) pf(v, c + 2); }
          cmp(cur);
          __syncthreads();
        }

        float pgh[2], phh[2];
#pragma unroll
        for (int i = 0; i < 2; ++i) {
          int r = row0 + ty * 2 + i, c0 = col32 + tx * 2;
          float G0 = ac[i][0] + __ldg(b2 + c0);
          float G1 = ac[i][1] + __ldg(b2 + c0 + 1);
          float y0 = __ldcg(&g_y[(size_t)r * H_ + c0]);
          float y1 = __ldcg(&g_y[(size_t)r * H_ + c0 + 1]);
          g_G[(size_t)r * H_ + c0] = G0;
          g_G[(size_t)r * H_ + c0 + 1] = G1;
          pgh[i] = fmaf(G0, y0, G1 * y1);
          phh[i] = fmaf(y0, y0, y1 * y1);
        }
#pragma unroll
        for (int o = 1; o < 16; o <<= 1) {
#pragma unroll
          for (int i = 0; i < 2; ++i) {
            pgh[i] += __shfl_xor_sync(0xffffffffu, pgh[i], o);
            phh[i] += __shfl_xor_sync(0xffffffffu, phh[i], o);
          }
        }
        if (tx == 0) {
#pragma unroll
          for (int i = 0; i < 2; ++i) {
            int r = row0 + ty * 2 + i;
            g_pGH[cb * B_ + r] = pgh[i];
            g_pHH[cb * B_ + r] = phh[i];
          }
        }
      }
      gridbar();

      // ---- update: proj, k_s, RK accumulate, next y / final h
      {
        const float wk = (s == 1 || s == 2) ? 2.f : 1.f;
        int r = bid * 4 + (tid >> 7);
        int c0 = (tid & 127) * 4;
        float sgh = 0.f, shh = 0.f;
#pragma unroll
        for (int p = 0; p < 16; ++p) {
          sgh += __ldcg(&g_pGH[p * B_ + r]);
          shh += __ldcg(&g_pHH[p * B_ + r]);
        }
        float proj = sgh / (shh + 1e-8f);
        const float* hb = out + (size_t)t * B_ * H_ + (size_t)r * H_;
#pragma unroll
        for (int j = 0; j < 4; ++j) {
          int c = c0 + j;
          float y = __ldcg(&g_y[(size_t)r * H_ + c]);
          float G = __ldcg(&g_G[(size_t)r * H_ + c]);
          float k = G - proj * y;
          float a = (s == 0) ? 0.f : __ldcg(&g_acc[(size_t)r * H_ + c]);
          float na = a + wk * k;
          float hbv = __ldcg(&hb[c]);
          if (s < 3) {
            g_acc[(size_t)r * H_ + c] = na;
            float cs = (s == 2) ? 1.0f : 0.5f;
            g_y[(size_t)r * H_ + c] = hbv + cs * dt * k;
          } else {
            g_h[(size_t)r * H_ + c] = hbv + (dt * (1.f / 6.f)) * na;
          }
        }
      }
      gridbar();
    }
  }
}

extern "C" void kernel_launch(void* const* d_in, const int* in_sizes, int n_in,
                              void* d_out, int out_size) {
  (void)in_sizes; (void)n_in; (void)out_size;
  ode_kernel<<<NBLK, TPB>>>(
      (const float*)d_in[0], (const float*)d_in[1], (const float*)d_in[2],
      (const float*)d_in[3], (const float*)d_in[4], (const float*)d_in[5],
      (const float*)d_in[6], (const float*)d_in[7], (const float*)d_in[8],
      (const float*)d_in[9], (float*)d_out);
}